// round 3
// baseline (speedup 1.0000x reference)
#include <cuda_runtime.h>

// Problem constants
constexpr int Bc = 64;     // batch
constexpr int Tc = 256;    // sequence length
constexpr int Cc = 384;    // channels
constexpr int Hc = 6;      // heads
constexpr int Dc = 64;     // head dim

constexpr int BH = Bc * Hc;          // 384
constexpr int BT = Bc * Tc;          // 16384

// Scratch (static device arrays: allocation-free rule)
__device__ float g_Q[(size_t)BH * Tc * Dc];     // [B,H,T,D]
__device__ float g_K[(size_t)BH * Tc * Dc];
__device__ float g_V[(size_t)BH * Tc * Dc];
__device__ float g_att[(size_t)BT * Cc];        // [B,T,H*D]

// ---------------------------------------------------------------------------
// Kernel 1: QKV projection. grid = (T/64, 3, B*H), block = (16,16)
// Computes O[bh][t][d] = sum_c x[b][t][c] * W[h][c][d] for W in {Wq,Wk,Wv}
// ---------------------------------------------------------------------------
__global__ void __launch_bounds__(256, 4)
qkv_kernel(const float* __restrict__ x,
           const float* __restrict__ Wq,
           const float* __restrict__ Wk,
           const float* __restrict__ Wv) {
    const int bh = blockIdx.z;
    const int b  = bh / Hc;
    const int h  = bh % Hc;
    const int which = blockIdx.y;
    const int t0 = blockIdx.x * 64;

    const float* W = (which == 0 ? Wq : (which == 1 ? Wk : Wv)) + (size_t)h * Cc * Dc;
    float* O = (which == 0 ? g_Q : (which == 1 ? g_K : g_V)) + (size_t)bh * Tc * Dc;
    const float* xbase = x + (size_t)b * Tc * Cc + (size_t)t0 * Cc;

    __shared__ float Xs[64][17];   // [t][k] padded
    __shared__ float Ws[16][64];   // [k][d]

    const int tx = threadIdx.x, ty = threadIdx.y;
    const int tid = ty * 16 + tx;

    float acc[4][4];
    #pragma unroll
    for (int i = 0; i < 4; i++)
        #pragma unroll
        for (int j = 0; j < 4; j++) acc[i][j] = 0.f;

    for (int kk = 0; kk < Cc; kk += 16) {
        // load X tile 64x16 (float4 per thread)
        {
            int r = tid >> 2, c4 = (tid & 3) * 4;
            float4 v = *reinterpret_cast<const float4*>(xbase + (size_t)r * Cc + kk + c4);
            Xs[r][c4 + 0] = v.x; Xs[r][c4 + 1] = v.y;
            Xs[r][c4 + 2] = v.z; Xs[r][c4 + 3] = v.w;
        }
        // load W tile 16x64
        {
            int r = tid >> 4, c4 = (tid & 15) * 4;
            float4 v = *reinterpret_cast<const float4*>(W + (size_t)(kk + r) * Dc + c4);
            *reinterpret_cast<float4*>(&Ws[r][c4]) = v;
        }
        __syncthreads();

        #pragma unroll
        for (int c = 0; c < 16; c++) {
            float a0 = Xs[ty * 4 + 0][c];
            float a1 = Xs[ty * 4 + 1][c];
            float a2 = Xs[ty * 4 + 2][c];
            float a3 = Xs[ty * 4 + 3][c];
            float4 bv = *reinterpret_cast<const float4*>(&Ws[c][tx * 4]);
            acc[0][0] += a0 * bv.x; acc[0][1] += a0 * bv.y; acc[0][2] += a0 * bv.z; acc[0][3] += a0 * bv.w;
            acc[1][0] += a1 * bv.x; acc[1][1] += a1 * bv.y; acc[1][2] += a1 * bv.z; acc[1][3] += a1 * bv.w;
            acc[2][0] += a2 * bv.x; acc[2][1] += a2 * bv.y; acc[2][2] += a2 * bv.z; acc[2][3] += a2 * bv.w;
            acc[3][0] += a3 * bv.x; acc[3][1] += a3 * bv.y; acc[3][2] += a3 * bv.z; acc[3][3] += a3 * bv.w;
        }
        __syncthreads();
    }

    #pragma unroll
    for (int i = 0; i < 4; i++) {
        int row = t0 + ty * 4 + i;
        float4 o;
        o.x = acc[i][0]; o.y = acc[i][1]; o.z = acc[i][2]; o.w = acc[i][3];
        *reinterpret_cast<float4*>(O + (size_t)row * Dc + tx * 4) = o;
    }
}

// ---------------------------------------------------------------------------
// Kernel 2: causal attention. grid = (BH, T/QB), block = QB threads.
// Each CTA handles QB=128 query rows of one (b,h); thread-per-query online
// softmax; K/V streamed through 64KB smem in 128-key chunks; causally-dead
// key chunks are skipped entirely. 3 CTAs/SM resident (regs+smem both fit).
// Writes att in [B,T,H*D] layout.
// ---------------------------------------------------------------------------
constexpr int CH = 128;  // keys per chunk
constexpr int QB = 128;  // queries per CTA

__global__ void __launch_bounds__(QB, 3)
attn_kernel() {
    const int bh = blockIdx.x;
    const int b = bh / Hc;
    const int h = bh % Hc;
    const int qc = blockIdx.y;              // query chunk index
    const int t = qc * QB + threadIdx.x;    // this thread's query row
    const int tl = threadIdx.x;

    extern __shared__ float smem[];
    float* Ks = smem;                 // [CH][D]
    float* Vs = smem + CH * Dc;       // [CH][D]

    // load q row into registers (16 x float4)
    float4 q4[16];
    const float4* qg = reinterpret_cast<const float4*>(g_Q + ((size_t)bh * Tc + t) * Dc);
    #pragma unroll
    for (int i = 0; i < 16; i++) q4[i] = qg[i];

    float m = -1e30f, l = 0.f;
    float4 acc[16];
    #pragma unroll
    for (int i = 0; i < 16; i++) acc[i] = make_float4(0.f, 0.f, 0.f, 0.f);

    const float scale = 0.125f;  // 1/sqrt(64)
    const int qEnd = qc * QB + QB - 1;   // max query index in this CTA

    for (int c0 = 0; c0 <= qEnd; c0 += CH) {   // skip causally-dead chunks
        __syncthreads();
        // cooperative load of K,V chunk (coalesced float4): 2048 float4 each
        const float4* kg = reinterpret_cast<const float4*>(g_K + ((size_t)bh * Tc + c0) * Dc);
        const float4* vg = reinterpret_cast<const float4*>(g_V + ((size_t)bh * Tc + c0) * Dc);
        float4* Ks4 = reinterpret_cast<float4*>(Ks);
        float4* Vs4 = reinterpret_cast<float4*>(Vs);
        #pragma unroll
        for (int i = 0; i < (CH * Dc / 4) / QB; i++) {
            Ks4[i * QB + tl] = kg[i * QB + tl];
            Vs4[i * QB + tl] = vg[i * QB + tl];
        }
        __syncthreads();

        const int nKeys = min(t - c0 + 1, CH);   // visible keys in this chunk
        int sc = 0;

        // 2-key unrolled main loop: two independent dot chains for ILP
        for (; sc + 2 <= nKeys; sc += 2) {
            const float4* k0 = reinterpret_cast<const float4*>(Ks + (sc + 0) * Dc);
            const float4* k1 = reinterpret_cast<const float4*>(Ks + (sc + 1) * Dc);
            float4 d0 = make_float4(0.f, 0.f, 0.f, 0.f);
            float4 d1 = make_float4(0.f, 0.f, 0.f, 0.f);
            #pragma unroll
            for (int i = 0; i < 16; i++) {
                float4 a = q4[i];
                float4 kv0 = k0[i];
                float4 kv1 = k1[i];
                d0.x += a.x * kv0.x; d0.y += a.y * kv0.y;
                d0.z += a.z * kv0.z; d0.w += a.w * kv0.w;
                d1.x += a.x * kv1.x; d1.y += a.y * kv1.y;
                d1.z += a.z * kv1.z; d1.w += a.w * kv1.w;
            }
            float x0 = ((d0.x + d0.y) + (d0.z + d0.w)) * scale;
            float x1 = ((d1.x + d1.y) + (d1.z + d1.w)) * scale;

            float mn = fmaxf(m, fmaxf(x0, x1));
            float p0 = __expf(x0 - mn);
            float p1 = __expf(x1 - mn);
            float corr = __expf(m - mn);
            l = l * corr + p0 + p1;
            const float4* v0 = reinterpret_cast<const float4*>(Vs + (sc + 0) * Dc);
            const float4* v1 = reinterpret_cast<const float4*>(Vs + (sc + 1) * Dc);
            #pragma unroll
            for (int i = 0; i < 16; i++) {
                float4 a = acc[i];
                float4 va = v0[i];
                float4 vb = v1[i];
                a.x = a.x * corr + p0 * va.x + p1 * vb.x;
                a.y = a.y * corr + p0 * va.y + p1 * vb.y;
                a.z = a.z * corr + p0 * va.z + p1 * vb.z;
                a.w = a.w * corr + p0 * va.w + p1 * vb.w;
                acc[i] = a;
            }
            m = mn;
        }

        // remainder (0 or 1 key)
        for (; sc < nKeys; ++sc) {
            const float4* kk = reinterpret_cast<const float4*>(Ks + sc * Dc);
            float4 d4 = make_float4(0.f, 0.f, 0.f, 0.f);
            #pragma unroll
            for (int i = 0; i < 16; i++) {
                float4 kv = kk[i];
                d4.x += q4[i].x * kv.x;
                d4.y += q4[i].y * kv.y;
                d4.z += q4[i].z * kv.z;
                d4.w += q4[i].w * kv.w;
            }
            float xv = ((d4.x + d4.y) + (d4.z + d4.w)) * scale;
            float mn = fmaxf(m, xv);
            float p = __expf(xv - mn);
            float corr = __expf(m - mn);
            l = l * corr + p;
            const float4* vv = reinterpret_cast<const float4*>(Vs + sc * Dc);
            #pragma unroll
            for (int i = 0; i < 16; i++) {
                float4 v = vv[i];
                acc[i].x = acc[i].x * corr + p * v.x;
                acc[i].y = acc[i].y * corr + p * v.y;
                acc[i].z = acc[i].z * corr + p * v.z;
                acc[i].w = acc[i].w * corr + p * v.w;
            }
            m = mn;
        }
    }

    const float inv = 1.f / l;
    float* og = g_att + ((size_t)b * Tc + t) * Cc + h * Dc;
    #pragma unroll
    for (int i = 0; i < 16; i++) {
        float4 o;
        o.x = acc[i].x * inv; o.y = acc[i].y * inv;
        o.z = acc[i].z * inv; o.w = acc[i].w * inv;
        *reinterpret_cast<float4*>(og + i * 4) = o;
    }
}

// ---------------------------------------------------------------------------
// Kernel 3: output projection  out = att @ Wp^T + bp
// grid = (C/64, BT/64), block = (16,16). out[m][n] = sum_k att[m][k]*Wp[n][k]
// ---------------------------------------------------------------------------
__global__ void __launch_bounds__(256, 4)
proj_kernel(const float* __restrict__ Wp,
            const float* __restrict__ bp,
            float* __restrict__ out) {
    const int n0 = blockIdx.x * 64;
    const int m0 = blockIdx.y * 64;

    __shared__ float As[64][17];   // [m][k] padded
    __shared__ float Bs[16][68];   // [k][n] padded

    const int tx = threadIdx.x, ty = threadIdx.y;
    const int tid = ty * 16 + tx;

    float acc[4][4];
    #pragma unroll
    for (int i = 0; i < 4; i++)
        #pragma unroll
        for (int j = 0; j < 4; j++) acc[i][j] = 0.f;

    for (int kk = 0; kk < Cc; kk += 16) {
        // load att tile 64x16
        {
            int r = tid >> 2, c4 = (tid & 3) * 4;
            float4 v = *reinterpret_cast<const float4*>(g_att + (size_t)(m0 + r) * Cc + kk + c4);
            As[r][c4 + 0] = v.x; As[r][c4 + 1] = v.y;
            As[r][c4 + 2] = v.z; As[r][c4 + 3] = v.w;
        }
        // load Wp tile transposed: Bs[k][n] = Wp[n][k]
        {
            int r = tid >> 2, c4 = (tid & 3) * 4;   // r = n index, c4 = k offset
            float4 v = *reinterpret_cast<const float4*>(Wp + (size_t)(n0 + r) * Cc + kk + c4);
            Bs[c4 + 0][r] = v.x; Bs[c4 + 1][r] = v.y;
            Bs[c4 + 2][r] = v.z; Bs[c4 + 3][r] = v.w;
        }
        __syncthreads();

        #pragma unroll
        for (int c = 0; c < 16; c++) {
            float a0 = As[ty * 4 + 0][c];
            float a1 = As[ty * 4 + 1][c];
            float a2 = As[ty * 4 + 2][c];
            float a3 = As[ty * 4 + 3][c];
            float4 bv = *reinterpret_cast<const float4*>(&Bs[c][tx * 4]);
            acc[0][0] += a0 * bv.x; acc[0][1] += a0 * bv.y; acc[0][2] += a0 * bv.z; acc[0][3] += a0 * bv.w;
            acc[1][0] += a1 * bv.x; acc[1][1] += a1 * bv.y; acc[1][2] += a1 * bv.z; acc[1][3] += a1 * bv.w;
            acc[2][0] += a2 * bv.x; acc[2][1] += a2 * bv.y; acc[2][2] += a2 * bv.z; acc[2][3] += a2 * bv.w;
            acc[3][0] += a3 * bv.x; acc[3][1] += a3 * bv.y; acc[3][2] += a3 * bv.z; acc[3][3] += a3 * bv.w;
        }
        __syncthreads();
    }

    float4 bpv = *reinterpret_cast<const float4*>(bp + n0 + tx * 4);
    #pragma unroll
    for (int i = 0; i < 4; i++) {
        int row = m0 + ty * 4 + i;
        float4 o;
        o.x = acc[i][0] + bpv.x; o.y = acc[i][1] + bpv.y;
        o.z = acc[i][2] + bpv.z; o.w = acc[i][3] + bpv.w;
        *reinterpret_cast<float4*>(out + (size_t)row * Cc + n0 + tx * 4) = o;
    }
}

// ---------------------------------------------------------------------------
extern "C" void kernel_launch(void* const* d_in, const int* in_sizes, int n_in,
                              void* d_out, int out_size) {
    const float* x  = (const float*)d_in[0];
    const float* Wq = (const float*)d_in[1];
    const float* Wk = (const float*)d_in[2];
    const float* Wv = (const float*)d_in[3];
    const float* Wp = (const float*)d_in[4];
    const float* bp = (const float*)d_in[5];
    float* out = (float*)d_out;

    // attention smem: 2 * CH * D * 4 = 64 KB (> 48 KB default)
    cudaFuncSetAttribute(attn_kernel, cudaFuncAttributeMaxDynamicSharedMemorySize,
                         2 * CH * Dc * (int)sizeof(float));

    dim3 blk(16, 16);
    dim3 g1(Tc / 64, 3, BH);
    qkv_kernel<<<g1, blk>>>(x, Wq, Wk, Wv);

    dim3 g2(BH, Tc / QB);
    attn_kernel<<<g2, QB, 2 * CH * Dc * sizeof(float)>>>();

    dim3 g3(Cc / 64, BT / 64);
    proj_kernel<<<g3, blk>>>(Wp, bp, out);
}

// round 8
// speedup vs baseline: 1.1446x; 1.1446x over previous
#include <cuda_runtime.h>

// Problem constants
constexpr int Bc = 64;     // batch
constexpr int Tc = 256;    // sequence length
constexpr int Cc = 384;    // channels
constexpr int Hc = 6;      // heads
constexpr int Dc = 64;     // head dim

constexpr int BH = Bc * Hc;          // 384
constexpr int BT = Bc * Tc;          // 16384
constexpr int NQKV = 3 * Cc;         // 1152 fused output cols (q|k|v)

// Scratch (static device arrays: allocation-free rule)
__device__ float g_Q[(size_t)BH * Tc * Dc];     // [B,H,T,D]
__device__ float g_K[(size_t)BH * Tc * Dc];
__device__ float g_V[(size_t)BH * Tc * Dc];
__device__ float g_att[(size_t)BT * Cc];        // [B,T,H*D]

// ---------------------------------------------------------------------------
// Kernel 1: fused QKV projection as one GEMM.
//   out[m][n] = sum_c x[m][c] * Wcat[c][n],  m in [0,BT), n in [0,1152)
//   n = which*384 + h*64 + d ;  W_which[h][c][d]
// 128x128 tiles, 256 threads, 8x8 per thread, K-step 16.
// Smem tiles transposed [k][m] / [k][n] so inner loads are float4.
// grid = (NQKV/128 = 9, BT/128 = 128)
// ---------------------------------------------------------------------------
constexpr int TM = 128, TN = 128, TK = 16;
constexpr int PAD = 4;

__global__ void __launch_bounds__(256, 2)
qkv_kernel(const float* __restrict__ x,
           const float* __restrict__ Wq,
           const float* __restrict__ Wk,
           const float* __restrict__ Wv) {
    const int n0 = blockIdx.x * TN;
    const int m0 = blockIdx.y * TM;

    const int which = n0 / Cc;                 // 0=q,1=k,2=v (tile never spans)
    const int n0h   = n0 % Cc;                 // offset within the which-band
    const float* __restrict__ W =
        (which == 0 ? Wq : (which == 1 ? Wk : Wv));
    float* __restrict__ Obase =
        (which == 0 ? g_Q : (which == 1 ? g_K : g_V));

    __shared__ float Xs[TK][TM + PAD];   // [k][m]
    __shared__ float Ws[TK][TN + PAD];   // [k][n]

    const int tx = threadIdx.x & 15;     // n group
    const int ty = threadIdx.x >> 4;     // m group
    const int tid = threadIdx.x;

    float acc[8][8];
    #pragma unroll
    for (int i = 0; i < 8; i++)
        #pragma unroll
        for (int j = 0; j < 8; j++) acc[i][j] = 0.f;

    for (int kk = 0; kk < Cc; kk += TK) {
        // --- load X tile (TM x TK) transposed into Xs[k][m] ---
        // 512 float4 loads; thread handles idx = tid, tid+256
        #pragma unroll
        for (int u = 0; u < 2; u++) {
            int idx = tid + u * 256;
            int r  = idx >> 2;              // m row 0..127
            int c4 = (idx & 3) * 4;         // k offset
            float4 v = *reinterpret_cast<const float4*>(
                x + (size_t)(m0 + r) * Cc + kk + c4);
            Xs[c4 + 0][r] = v.x; Xs[c4 + 1][r] = v.y;
            Xs[c4 + 2][r] = v.z; Xs[c4 + 3][r] = v.w;
        }
        // --- load W tile (TK x TN) into Ws[k][n] ---
        // source col n0h+nl: h=(n0h+nl)/64, d=(n0h+nl)%64; row kk+r
        #pragma unroll
        for (int u = 0; u < 2; u++) {
            int idx = tid + u * 256;
            int r   = idx >> 5;             // k row 0..15
            int nl4 = (idx & 31) * 4;       // n offset (float4 granular)
            int nn  = n0h + nl4;
            int h   = nn >> 6;
            int d   = nn & 63;
            float4 v = *reinterpret_cast<const float4*>(
                W + ((size_t)h * Cc + (kk + r)) * Dc + d);
            *reinterpret_cast<float4*>(&Ws[r][nl4]) = v;
        }
        __syncthreads();

        #pragma unroll
        for (int c = 0; c < TK; c++) {
            float4 a0 = *reinterpret_cast<const float4*>(&Xs[c][ty * 8]);
            float4 a1 = *reinterpret_cast<const float4*>(&Xs[c][ty * 8 + 4]);
            float4 b0 = *reinterpret_cast<const float4*>(&Ws[c][tx * 8]);
            float4 b1 = *reinterpret_cast<const float4*>(&Ws[c][tx * 8 + 4]);
            float a[8] = {a0.x, a0.y, a0.z, a0.w, a1.x, a1.y, a1.z, a1.w};
            float bb[8] = {b0.x, b0.y, b0.z, b0.w, b1.x, b1.y, b1.z, b1.w};
            #pragma unroll
            for (int i = 0; i < 8; i++)
                #pragma unroll
                for (int j = 0; j < 8; j++)
                    acc[i][j] += a[i] * bb[j];
        }
        __syncthreads();
    }

    // store: rows m0+ty*8+i ; cols n0 + tx*8 + j (one head per thread strip)
    const int nl = tx * 8;
    const int h  = (n0h + nl) >> 6;         // nl multiple of 8; strip within head
    const int d0 = (n0h + nl) & 63;
    #pragma unroll
    for (int i = 0; i < 8; i++) {
        int m = m0 + ty * 8 + i;
        int b = m >> 8;                      // /Tc
        int t = m & 255;                     // %Tc
        float* O = Obase + (((size_t)(b * Hc + h) * Tc + t) * Dc + d0);
        float4 o0, o1;
        o0.x = acc[i][0]; o0.y = acc[i][1]; o0.z = acc[i][2]; o0.w = acc[i][3];
        o1.x = acc[i][4]; o1.y = acc[i][5]; o1.z = acc[i][6]; o1.w = acc[i][7];
        *reinterpret_cast<float4*>(O)     = o0;
        *reinterpret_cast<float4*>(O + 4) = o1;
    }
}

// ---------------------------------------------------------------------------
// Kernel 2: causal attention. grid = (BH, T/QB), block = QB threads.
// Thread-per-query online softmax; K/V streamed through 64KB smem in
// 128-key chunks; causally-dead chunks skipped. (unchanged from passing R3)
// ---------------------------------------------------------------------------
constexpr int CH = 128;  // keys per chunk
constexpr int QB = 128;  // queries per CTA

__global__ void __launch_bounds__(QB, 3)
attn_kernel() {
    const int bh = blockIdx.x;
    const int b = bh / Hc;
    const int h = bh % Hc;
    const int qc = blockIdx.y;
    const int t = qc * QB + threadIdx.x;
    const int tl = threadIdx.x;

    extern __shared__ float smem[];
    float* Ks = smem;
    float* Vs = smem + CH * Dc;

    float4 q4[16];
    const float4* qg = reinterpret_cast<const float4*>(g_Q + ((size_t)bh * Tc + t) * Dc);
    #pragma unroll
    for (int i = 0; i < 16; i++) q4[i] = qg[i];

    float m = -1e30f, l = 0.f;
    float4 acc[16];
    #pragma unroll
    for (int i = 0; i < 16; i++) acc[i] = make_float4(0.f, 0.f, 0.f, 0.f);

    const float scale = 0.125f;
    const int qEnd = qc * QB + QB - 1;

    for (int c0 = 0; c0 <= qEnd; c0 += CH) {
        __syncthreads();
        const float4* kg = reinterpret_cast<const float4*>(g_K + ((size_t)bh * Tc + c0) * Dc);
        const float4* vg = reinterpret_cast<const float4*>(g_V + ((size_t)bh * Tc + c0) * Dc);
        float4* Ks4 = reinterpret_cast<float4*>(Ks);
        float4* Vs4 = reinterpret_cast<float4*>(Vs);
        #pragma unroll
        for (int i = 0; i < (CH * Dc / 4) / QB; i++) {
            Ks4[i * QB + tl] = kg[i * QB + tl];
            Vs4[i * QB + tl] = vg[i * QB + tl];
        }
        __syncthreads();

        const int nKeys = min(t - c0 + 1, CH);
        int sc = 0;

        for (; sc + 2 <= nKeys; sc += 2) {
            const float4* k0 = reinterpret_cast<const float4*>(Ks + (sc + 0) * Dc);
            const float4* k1 = reinterpret_cast<const float4*>(Ks + (sc + 1) * Dc);
            float4 d0 = make_float4(0.f, 0.f, 0.f, 0.f);
            float4 d1 = make_float4(0.f, 0.f, 0.f, 0.f);
            #pragma unroll
            for (int i = 0; i < 16; i++) {
                float4 a = q4[i];
                float4 kv0 = k0[i];
                float4 kv1 = k1[i];
                d0.x += a.x * kv0.x; d0.y += a.y * kv0.y;
                d0.z += a.z * kv0.z; d0.w += a.w * kv0.w;
                d1.x += a.x * kv1.x; d1.y += a.y * kv1.y;
                d1.z += a.z * kv1.z; d1.w += a.w * kv1.w;
            }
            float x0 = ((d0.x + d0.y) + (d0.z + d0.w)) * scale;
            float x1 = ((d1.x + d1.y) + (d1.z + d1.w)) * scale;

            float mn = fmaxf(m, fmaxf(x0, x1));
            float p0 = __expf(x0 - mn);
            float p1 = __expf(x1 - mn);
            float corr = __expf(m - mn);
            l = l * corr + p0 + p1;
            const float4* v0 = reinterpret_cast<const float4*>(Vs + (sc + 0) * Dc);
            const float4* v1 = reinterpret_cast<const float4*>(Vs + (sc + 1) * Dc);
            #pragma unroll
            for (int i = 0; i < 16; i++) {
                float4 a = acc[i];
                float4 va = v0[i];
                float4 vb = v1[i];
                a.x = a.x * corr + p0 * va.x + p1 * vb.x;
                a.y = a.y * corr + p0 * va.y + p1 * vb.y;
                a.z = a.z * corr + p0 * va.z + p1 * vb.z;
                a.w = a.w * corr + p0 * va.w + p1 * vb.w;
                acc[i] = a;
            }
            m = mn;
        }

        for (; sc < nKeys; ++sc) {
            const float4* kk = reinterpret_cast<const float4*>(Ks + sc * Dc);
            float4 d4 = make_float4(0.f, 0.f, 0.f, 0.f);
            #pragma unroll
            for (int i = 0; i < 16; i++) {
                float4 kv = kk[i];
                d4.x += q4[i].x * kv.x;
                d4.y += q4[i].y * kv.y;
                d4.z += q4[i].z * kv.z;
                d4.w += q4[i].w * kv.w;
            }
            float xv = ((d4.x + d4.y) + (d4.z + d4.w)) * scale;
            float mn = fmaxf(m, xv);
            float p = __expf(xv - mn);
            float corr = __expf(m - mn);
            l = l * corr + p;
            const float4* vv = reinterpret_cast<const float4*>(Vs + sc * Dc);
            #pragma unroll
            for (int i = 0; i < 16; i++) {
                float4 v = vv[i];
                acc[i].x = acc[i].x * corr + p * v.x;
                acc[i].y = acc[i].y * corr + p * v.y;
                acc[i].z = acc[i].z * corr + p * v.z;
                acc[i].w = acc[i].w * corr + p * v.w;
            }
            m = mn;
        }
    }

    const float inv = 1.f / l;
    float* og = g_att + ((size_t)b * Tc + t) * Cc + h * Dc;
    #pragma unroll
    for (int i = 0; i < 16; i++) {
        float4 o;
        o.x = acc[i].x * inv; o.y = acc[i].y * inv;
        o.z = acc[i].z * inv; o.w = acc[i].w * inv;
        *reinterpret_cast<float4*>(og + i * 4) = o;
    }
}

// ---------------------------------------------------------------------------
// Kernel 3: output projection  out = att @ Wp^T + bp
// 128x128 tiles, 8x8 per thread. grid = (Cc/128 = 3, BT/128 = 128)
// ---------------------------------------------------------------------------
__global__ void __launch_bounds__(256, 2)
proj_kernel(const float* __restrict__ Wp,
            const float* __restrict__ bp,
            float* __restrict__ out) {
    const int n0 = blockIdx.x * TN;
    const int m0 = blockIdx.y * TM;

    __shared__ float As[TK][TM + PAD];   // [k][m]
    __shared__ float Bs[TK][TN + PAD];   // [k][n]  (= Wp transposed)

    const int tx = threadIdx.x & 15;
    const int ty = threadIdx.x >> 4;
    const int tid = threadIdx.x;

    float acc[8][8];
    #pragma unroll
    for (int i = 0; i < 8; i++)
        #pragma unroll
        for (int j = 0; j < 8; j++) acc[i][j] = 0.f;

    for (int kk = 0; kk < Cc; kk += TK) {
        // att tile (TM x TK) -> As[k][m]
        #pragma unroll
        for (int u = 0; u < 2; u++) {
            int idx = tid + u * 256;
            int r  = idx >> 2;
            int c4 = (idx & 3) * 4;
            float4 v = *reinterpret_cast<const float4*>(
                g_att + (size_t)(m0 + r) * Cc + kk + c4);
            As[c4 + 0][r] = v.x; As[c4 + 1][r] = v.y;
            As[c4 + 2][r] = v.z; As[c4 + 3][r] = v.w;
        }
        // Wp tile transposed: Bs[k][n] = Wp[n0+n][kk+k]
        #pragma unroll
        for (int u = 0; u < 2; u++) {
            int idx = tid + u * 256;
            int nl = idx >> 2;              // n 0..127
            int c4 = (idx & 3) * 4;         // k offset
            float4 v = *reinterpret_cast<const float4*>(
                Wp + (size_t)(n0 + nl) * Cc + kk + c4);
            Bs[c4 + 0][nl] = v.x; Bs[c4 + 1][nl] = v.y;
            Bs[c4 + 2][nl] = v.z; Bs[c4 + 3][nl] = v.w;
        }
        __syncthreads();

        #pragma unroll
        for (int c = 0; c < TK; c++) {
            float4 a0 = *reinterpret_cast<const float4*>(&As[c][ty * 8]);
            float4 a1 = *reinterpret_cast<const float4*>(&As[c][ty * 8 + 4]);
            float4 b0 = *reinterpret_cast<const float4*>(&Bs[c][tx * 8]);
            float4 b1 = *reinterpret_cast<const float4*>(&Bs[c][tx * 8 + 4]);
            float a[8] = {a0.x, a0.y, a0.z, a0.w, a1.x, a1.y, a1.z, a1.w};
            float bb[8] = {b0.x, b0.y, b0.z, b0.w, b1.x, b1.y, b1.z, b1.w};
            #pragma unroll
            for (int i = 0; i < 8; i++)
                #pragma unroll
                for (int j = 0; j < 8; j++)
                    acc[i][j] += a[i] * bb[j];
        }
        __syncthreads();
    }

    float4 bp0 = *reinterpret_cast<const float4*>(bp + n0 + tx * 8);
    float4 bp1 = *reinterpret_cast<const float4*>(bp + n0 + tx * 8 + 4);
    #pragma unroll
    for (int i = 0; i < 8; i++) {
        int m = m0 + ty * 8 + i;
        float* O = out + (size_t)m * Cc + n0 + tx * 8;
        float4 o0, o1;
        o0.x = acc[i][0] + bp0.x; o0.y = acc[i][1] + bp0.y;
        o0.z = acc[i][2] + bp0.z; o0.w = acc[i][3] + bp0.w;
        o1.x = acc[i][4] + bp1.x; o1.y = acc[i][5] + bp1.y;
        o1.z = acc[i][6] + bp1.z; o1.w = acc[i][7] + bp1.w;
        *reinterpret_cast<float4*>(O)     = o0;
        *reinterpret_cast<float4*>(O + 4) = o1;
    }
}

// ---------------------------------------------------------------------------
extern "C" void kernel_launch(void* const* d_in, const int* in_sizes, int n_in,
                              void* d_out, int out_size) {
    const float* x  = (const float*)d_in[0];
    const float* Wq = (const float*)d_in[1];
    const float* Wk = (const float*)d_in[2];
    const float* Wv = (const float*)d_in[3];
    const float* Wp = (const float*)d_in[4];
    const float* bp = (const float*)d_in[5];
    float* out = (float*)d_out;

    cudaFuncSetAttribute(attn_kernel, cudaFuncAttributeMaxDynamicSharedMemorySize,
                         2 * CH * Dc * (int)sizeof(float));

    dim3 g1(NQKV / TN, BT / TM);          // (9, 128)
    qkv_kernel<<<g1, 256>>>(x, Wq, Wk, Wv);

    dim3 g2(BH, Tc / QB);
    attn_kernel<<<g2, QB, 2 * CH * Dc * sizeof(float)>>>();

    dim3 g3(Cc / TN, BT / TM);            // (3, 128)
    proj_kernel<<<g3, 256>>>(Wp, bp, out);
}

// round 10
// speedup vs baseline: 1.2087x; 1.0560x over previous
#include <cuda_runtime.h>

// Problem constants
constexpr int Bc = 64;     // batch
constexpr int Tc = 256;    // sequence length
constexpr int Cc = 384;    // channels
constexpr int Hc = 6;      // heads
constexpr int Dc = 64;     // head dim

constexpr int BH = Bc * Hc;          // 384
constexpr int BT = Bc * Tc;          // 16384
constexpr int NQKV = 3 * Cc;         // 1152 fused output cols (q|k|v)

// Scratch (static device arrays: allocation-free rule)
__device__ float g_Q[(size_t)BH * Tc * Dc];     // [B,H,T,D]
__device__ float g_K[(size_t)BH * Tc * Dc];
__device__ float g_V[(size_t)BH * Tc * Dc];
__device__ float g_att[(size_t)BT * Cc];        // [B,T,H*D]

// ---------------------------------------------------------------------------
// GEMM tiling: 128x128 tiles, 256 threads, 8x8 per thread as 2+2 strips of 4.
// Thread (tx,ty), tx=tid&15, ty=tid>>4:
//   n columns: [tx*4, tx*4+4) and [64+tx*4, 64+tx*4+4)
//   m rows:    [ty*4, ty*4+4) and [64+ty*4, 64+ty*4+4)
// Inner-loop smem loads are 256B-contiguous float4 strips -> 2-phase LDS.128
// (vs 4-phase for 32B-strided 8-wide strips). A-loads are 2-addr broadcasts.
// ---------------------------------------------------------------------------
constexpr int TM = 128, TN = 128, TK = 16;
constexpr int PAD = 4;

__global__ void __launch_bounds__(256, 2)
qkv_kernel(const float* __restrict__ x,
           const float* __restrict__ Wq,
           const float* __restrict__ Wk,
           const float* __restrict__ Wv) {
    const int n0 = blockIdx.x * TN;
    const int m0 = blockIdx.y * TM;

    const int which = n0 / Cc;                 // 0=q,1=k,2=v (tile never spans)
    const int n0h   = n0 % Cc;                 // offset within the which-band
    const float* __restrict__ W =
        (which == 0 ? Wq : (which == 1 ? Wk : Wv));
    float* __restrict__ Obase =
        (which == 0 ? g_Q : (which == 1 ? g_K : g_V));

    __shared__ float Xs[TK][TM + PAD];   // [k][m]
    __shared__ float Ws[TK][TN + PAD];   // [k][n]

    const int tx = threadIdx.x & 15;     // n group
    const int ty = threadIdx.x >> 4;     // m group
    const int tid = threadIdx.x;

    float acc[8][8];                     // [m: 4 lo + 4 hi][n: 4 lo + 4 hi]
    #pragma unroll
    for (int i = 0; i < 8; i++)
        #pragma unroll
        for (int j = 0; j < 8; j++) acc[i][j] = 0.f;

    for (int kk = 0; kk < Cc; kk += TK) {
        // --- load X tile (TM x TK) transposed into Xs[k][m] ---
        #pragma unroll
        for (int u = 0; u < 2; u++) {
            int idx = tid + u * 256;
            int r  = idx >> 2;              // m row 0..127
            int c4 = (idx & 3) * 4;         // k offset
            float4 v = *reinterpret_cast<const float4*>(
                x + (size_t)(m0 + r) * Cc + kk + c4);
            Xs[c4 + 0][r] = v.x; Xs[c4 + 1][r] = v.y;
            Xs[c4 + 2][r] = v.z; Xs[c4 + 3][r] = v.w;
        }
        // --- load W tile (TK x TN) into Ws[k][n] ---
        #pragma unroll
        for (int u = 0; u < 2; u++) {
            int idx = tid + u * 256;
            int r   = idx >> 5;             // k row 0..15
            int nl4 = (idx & 31) * 4;       // n offset (float4 granular)
            int nn  = n0h + nl4;
            int h   = nn >> 6;
            int d   = nn & 63;
            float4 v = *reinterpret_cast<const float4*>(
                W + ((size_t)h * Cc + (kk + r)) * Dc + d);
            *reinterpret_cast<float4*>(&Ws[r][nl4]) = v;
        }
        __syncthreads();

        #pragma unroll
        for (int c = 0; c < TK; c++) {
            float4 a0 = *reinterpret_cast<const float4*>(&Xs[c][ty * 4]);
            float4 a1 = *reinterpret_cast<const float4*>(&Xs[c][64 + ty * 4]);
            float4 b0 = *reinterpret_cast<const float4*>(&Ws[c][tx * 4]);
            float4 b1 = *reinterpret_cast<const float4*>(&Ws[c][64 + tx * 4]);
            float a[8] = {a0.x, a0.y, a0.z, a0.w, a1.x, a1.y, a1.z, a1.w};
            float bb[8] = {b0.x, b0.y, b0.z, b0.w, b1.x, b1.y, b1.z, b1.w};
            #pragma unroll
            for (int i = 0; i < 8; i++)
                #pragma unroll
                for (int j = 0; j < 8; j++)
                    acc[i][j] += a[i] * bb[j];
        }
        __syncthreads();
    }

    // store: n strips of 4 stay within a 64-wide head (4 | 64)
    const int nlo = tx * 4, nhi = 64 + tx * 4;
    const int h_lo = (n0h + nlo) >> 6, d_lo = (n0h + nlo) & 63;
    const int h_hi = (n0h + nhi) >> 6, d_hi = (n0h + nhi) & 63;
    #pragma unroll
    for (int i = 0; i < 8; i++) {
        int m = m0 + (i < 4 ? ty * 4 + i : 64 + ty * 4 + (i - 4));
        int b = m >> 8;                      // /Tc
        int t = m & 255;                     // %Tc
        float* Olo = Obase + (((size_t)(b * Hc + h_lo) * Tc + t) * Dc + d_lo);
        float* Ohi = Obase + (((size_t)(b * Hc + h_hi) * Tc + t) * Dc + d_hi);
        float4 o0, o1;
        o0.x = acc[i][0]; o0.y = acc[i][1]; o0.z = acc[i][2]; o0.w = acc[i][3];
        o1.x = acc[i][4]; o1.y = acc[i][5]; o1.z = acc[i][6]; o1.w = acc[i][7];
        *reinterpret_cast<float4*>(Olo) = o0;
        *reinterpret_cast<float4*>(Ohi) = o1;
    }
}

// ---------------------------------------------------------------------------
// Kernel 2: causal attention. grid = (BH, T/QB), block = QB threads.
// Thread-per-query online softmax; K/V streamed through 64KB smem in
// 128-key chunks; causally-dead chunks skipped. (unchanged — passing lineage)
// ---------------------------------------------------------------------------
constexpr int CH = 128;  // keys per chunk
constexpr int QB = 128;  // queries per CTA

__global__ void __launch_bounds__(QB, 3)
attn_kernel() {
    const int bh = blockIdx.x;
    const int b = bh / Hc;
    const int h = bh % Hc;
    const int qc = blockIdx.y;
    const int t = qc * QB + threadIdx.x;
    const int tl = threadIdx.x;

    extern __shared__ float smem[];
    float* Ks = smem;
    float* Vs = smem + CH * Dc;

    float4 q4[16];
    const float4* qg = reinterpret_cast<const float4*>(g_Q + ((size_t)bh * Tc + t) * Dc);
    #pragma unroll
    for (int i = 0; i < 16; i++) q4[i] = qg[i];

    float m = -1e30f, l = 0.f;
    float4 acc[16];
    #pragma unroll
    for (int i = 0; i < 16; i++) acc[i] = make_float4(0.f, 0.f, 0.f, 0.f);

    const float scale = 0.125f;
    const int qEnd = qc * QB + QB - 1;

    for (int c0 = 0; c0 <= qEnd; c0 += CH) {
        __syncthreads();
        const float4* kg = reinterpret_cast<const float4*>(g_K + ((size_t)bh * Tc + c0) * Dc);
        const float4* vg = reinterpret_cast<const float4*>(g_V + ((size_t)bh * Tc + c0) * Dc);
        float4* Ks4 = reinterpret_cast<float4*>(Ks);
        float4* Vs4 = reinterpret_cast<float4*>(Vs);
        #pragma unroll
        for (int i = 0; i < (CH * Dc / 4) / QB; i++) {
            Ks4[i * QB + tl] = kg[i * QB + tl];
            Vs4[i * QB + tl] = vg[i * QB + tl];
        }
        __syncthreads();

        const int nKeys = min(t - c0 + 1, CH);
        int sc = 0;

        for (; sc + 2 <= nKeys; sc += 2) {
            const float4* k0 = reinterpret_cast<const float4*>(Ks + (sc + 0) * Dc);
            const float4* k1 = reinterpret_cast<const float4*>(Ks + (sc + 1) * Dc);
            float4 d0 = make_float4(0.f, 0.f, 0.f, 0.f);
            float4 d1 = make_float4(0.f, 0.f, 0.f, 0.f);
            #pragma unroll
            for (int i = 0; i < 16; i++) {
                float4 a = q4[i];
                float4 kv0 = k0[i];
                float4 kv1 = k1[i];
                d0.x += a.x * kv0.x; d0.y += a.y * kv0.y;
                d0.z += a.z * kv0.z; d0.w += a.w * kv0.w;
                d1.x += a.x * kv1.x; d1.y += a.y * kv1.y;
                d1.z += a.z * kv1.z; d1.w += a.w * kv1.w;
            }
            float x0 = ((d0.x + d0.y) + (d0.z + d0.w)) * scale;
            float x1 = ((d1.x + d1.y) + (d1.z + d1.w)) * scale;

            float mn = fmaxf(m, fmaxf(x0, x1));
            float p0 = __expf(x0 - mn);
            float p1 = __expf(x1 - mn);
            float corr = __expf(m - mn);
            l = l * corr + p0 + p1;
            const float4* v0 = reinterpret_cast<const float4*>(Vs + (sc + 0) * Dc);
            const float4* v1 = reinterpret_cast<const float4*>(Vs + (sc + 1) * Dc);
            #pragma unroll
            for (int i = 0; i < 16; i++) {
                float4 a = acc[i];
                float4 va = v0[i];
                float4 vb = v1[i];
                a.x = a.x * corr + p0 * va.x + p1 * vb.x;
                a.y = a.y * corr + p0 * va.y + p1 * vb.y;
                a.z = a.z * corr + p0 * va.z + p1 * vb.z;
                a.w = a.w * corr + p0 * va.w + p1 * vb.w;
                acc[i] = a;
            }
            m = mn;
        }

        for (; sc < nKeys; ++sc) {
            const float4* kk = reinterpret_cast<const float4*>(Ks + sc * Dc);
            float4 d4 = make_float4(0.f, 0.f, 0.f, 0.f);
            #pragma unroll
            for (int i = 0; i < 16; i++) {
                float4 kv = kk[i];
                d4.x += q4[i].x * kv.x;
                d4.y += q4[i].y * kv.y;
                d4.z += q4[i].z * kv.z;
                d4.w += q4[i].w * kv.w;
            }
            float xv = ((d4.x + d4.y) + (d4.z + d4.w)) * scale;
            float mn = fmaxf(m, xv);
            float p = __expf(xv - mn);
            float corr = __expf(m - mn);
            l = l * corr + p;
            const float4* vv = reinterpret_cast<const float4*>(Vs + sc * Dc);
            #pragma unroll
            for (int i = 0; i < 16; i++) {
                float4 v = vv[i];
                acc[i].x = acc[i].x * corr + p * v.x;
                acc[i].y = acc[i].y * corr + p * v.y;
                acc[i].z = acc[i].z * corr + p * v.z;
                acc[i].w = acc[i].w * corr + p * v.w;
            }
            m = mn;
        }
    }

    const float inv = 1.f / l;
    float* og = g_att + ((size_t)b * Tc + t) * Cc + h * Dc;
    #pragma unroll
    for (int i = 0; i < 16; i++) {
        float4 o;
        o.x = acc[i].x * inv; o.y = acc[i].y * inv;
        o.z = acc[i].z * inv; o.w = acc[i].w * inv;
        *reinterpret_cast<float4*>(og + i * 4) = o;
    }
}

// ---------------------------------------------------------------------------
// Kernel 3: output projection  out = att @ Wp^T + bp
// Same strip-of-4 tiling. grid = (Cc/128 = 3, BT/128 = 128)
// ---------------------------------------------------------------------------
__global__ void __launch_bounds__(256, 2)
proj_kernel(const float* __restrict__ Wp,
            const float* __restrict__ bp,
            float* __restrict__ out) {
    const int n0 = blockIdx.x * TN;
    const int m0 = blockIdx.y * TM;

    __shared__ float As[TK][TM + PAD];   // [k][m]
    __shared__ float Bs[TK][TN + PAD];   // [k][n]  (= Wp transposed)

    const int tx = threadIdx.x & 15;
    const int ty = threadIdx.x >> 4;
    const int tid = threadIdx.x;

    float acc[8][8];
    #pragma unroll
    for (int i = 0; i < 8; i++)
        #pragma unroll
        for (int j = 0; j < 8; j++) acc[i][j] = 0.f;

    for (int kk = 0; kk < Cc; kk += TK) {
        // att tile (TM x TK) -> As[k][m]
        #pragma unroll
        for (int u = 0; u < 2; u++) {
            int idx = tid + u * 256;
            int r  = idx >> 2;
            int c4 = (idx & 3) * 4;
            float4 v = *reinterpret_cast<const float4*>(
                g_att + (size_t)(m0 + r) * Cc + kk + c4);
            As[c4 + 0][r] = v.x; As[c4 + 1][r] = v.y;
            As[c4 + 2][r] = v.z; As[c4 + 3][r] = v.w;
        }
        // Wp tile transposed: Bs[k][n] = Wp[n0+n][kk+k]
        #pragma unroll
        for (int u = 0; u < 2; u++) {
            int idx = tid + u * 256;
            int nl = idx >> 2;              // n 0..127
            int c4 = (idx & 3) * 4;         // k offset
            float4 v = *reinterpret_cast<const float4*>(
                Wp + (size_t)(n0 + nl) * Cc + kk + c4);
            Bs[c4 + 0][nl] = v.x; Bs[c4 + 1][nl] = v.y;
            Bs[c4 + 2][nl] = v.z; Bs[c4 + 3][nl] = v.w;
        }
        __syncthreads();

        #pragma unroll
        for (int c = 0; c < TK; c++) {
            float4 a0 = *reinterpret_cast<const float4*>(&As[c][ty * 4]);
            float4 a1 = *reinterpret_cast<const float4*>(&As[c][64 + ty * 4]);
            float4 b0 = *reinterpret_cast<const float4*>(&Bs[c][tx * 4]);
            float4 b1 = *reinterpret_cast<const float4*>(&Bs[c][64 + tx * 4]);
            float a[8] = {a0.x, a0.y, a0.z, a0.w, a1.x, a1.y, a1.z, a1.w};
            float bb[8] = {b0.x, b0.y, b0.z, b0.w, b1.x, b1.y, b1.z, b1.w};
            #pragma unroll
            for (int i = 0; i < 8; i++)
                #pragma unroll
                for (int j = 0; j < 8; j++)
                    acc[i][j] += a[i] * bb[j];
        }
        __syncthreads();
    }

    float4 bp0 = *reinterpret_cast<const float4*>(bp + n0 + tx * 4);
    float4 bp1 = *reinterpret_cast<const float4*>(bp + n0 + 64 + tx * 4);
    #pragma unroll
    for (int i = 0; i < 8; i++) {
        int m = m0 + (i < 4 ? ty * 4 + i : 64 + ty * 4 + (i - 4));
        float* Olo = out + (size_t)m * Cc + n0 + tx * 4;
        float* Ohi = out + (size_t)m * Cc + n0 + 64 + tx * 4;
        float4 o0, o1;
        o0.x = acc[i][0] + bp0.x; o0.y = acc[i][1] + bp0.y;
        o0.z = acc[i][2] + bp0.z; o0.w = acc[i][3] + bp0.w;
        o1.x = acc[i][4] + bp1.x; o1.y = acc[i][5] + bp1.y;
        o1.z = acc[i][6] + bp1.z; o1.w = acc[i][7] + bp1.w;
        *reinterpret_cast<float4*>(Olo) = o0;
        *reinterpret_cast<float4*>(Ohi) = o1;
    }
}

// ---------------------------------------------------------------------------
extern "C" void kernel_launch(void* const* d_in, const int* in_sizes, int n_in,
                              void* d_out, int out_size) {
    const float* x  = (const float*)d_in[0];
    const float* Wq = (const float*)d_in[1];
    const float* Wk = (const float*)d_in[2];
    const float* Wv = (const float*)d_in[3];
    const float* Wp = (const float*)d_in[4];
    const float* bp = (const float*)d_in[5];
    float* out = (float*)d_out;

    cudaFuncSetAttribute(attn_kernel, cudaFuncAttributeMaxDynamicSharedMemorySize,
                         2 * CH * Dc * (int)sizeof(float));

    dim3 g1(NQKV / TN, BT / TM);          // (9, 128)
    qkv_kernel<<<g1, 256>>>(x, Wq, Wk, Wv);

    dim3 g2(BH, Tc / QB);
    attn_kernel<<<g2, QB, 2 * CH * Dc * sizeof(float)>>>();

    dim3 g3(Cc / TN, BT / TM);            // (3, 128)
    proj_kernel<<<g3, 256>>>(Wp, bp, out);
}

// round 13
// speedup vs baseline: 1.2280x; 1.0160x over previous
#include <cuda_runtime.h>

// Problem constants
constexpr int Bc = 64;     // batch
constexpr int Tc = 256;    // sequence length
constexpr int Cc = 384;    // channels
constexpr int Hc = 6;      // heads
constexpr int Dc = 64;     // head dim

constexpr int BH = Bc * Hc;          // 384
constexpr int BT = Bc * Tc;          // 16384
constexpr int NQKV = 3 * Cc;         // 1152 fused output cols (q|k|v)

// Scratch (static device arrays: allocation-free rule)
__device__ float g_Q[(size_t)BH * Tc * Dc];     // [B,H,T,D]
__device__ float g_K[(size_t)BH * Tc * Dc];
__device__ float g_V[(size_t)BH * Tc * Dc];
__device__ float g_att[(size_t)BT * Cc];        // [B,T,H*D]

// ---------------------------------------------------------------------------
// GEMM tiling: 128x128 tiles, 256 threads, 8x8/thread as 2+2 strips of 4
// (strips at tx*4 and 64+tx*4 -> 2-phase LDS.128, A-loads broadcast).
// Software pipeline — register-staged double buffering of both smem
// tiles, one __syncthreads per k-iteration; LDG of tile i+1 overlaps the
// 1024-FFMA compute of tile i.
// ---------------------------------------------------------------------------
constexpr int TM = 128, TN = 128, TK = 16;
constexpr int PAD = 4;
constexpr int NK = Cc / TK;          // 24

__global__ void __launch_bounds__(256, 2)
qkv_kernel(const float* __restrict__ x,
           const float* __restrict__ Wq,
           const float* __restrict__ Wk,
           const float* __restrict__ Wv) {
    const int n0 = blockIdx.x * TN;
    const int m0 = blockIdx.y * TM;

    const int which = n0 / Cc;                 // 0=q,1=k,2=v (tile never spans)
    const int n0h   = n0 % Cc;                 // offset within the which-band
    const float* __restrict__ W =
        (which == 0 ? Wq : (which == 1 ? Wk : Wv));
    float* __restrict__ Obase =
        (which == 0 ? g_Q : (which == 1 ? g_K : g_V));

    __shared__ float Xs[2][TK][TM + PAD];   // [buf][k][m]
    __shared__ float Ws[2][TK][TN + PAD];   // [buf][k][n]

    const int tx = threadIdx.x & 15;     // n group
    const int ty = threadIdx.x >> 4;     // m group
    const int tid = threadIdx.x;

    // --- load-index precompute ---
    // X: thread covers rows xr0 and xr0+64, k-cols [xc0, xc0+4)
    const int xr0 = tid >> 2;
    const int xc0 = (tid & 3) * 4;
    const float* xp0 = x + (size_t)(m0 + xr0) * Cc + xc0;
    const float* xp1 = x + (size_t)(m0 + xr0 + 64) * Cc + xc0;
    // W: thread covers k-rows wr0 and wr0+8 at n-col wn0 (same head/d for both)
    const int wr0 = tid >> 5;
    const int wn0 = (tid & 31) * 4;
    const int wh  = (n0h + wn0) >> 6;
    const int wd  = (n0h + wn0) & 63;

    float4 sx0, sx1, sw0, sw1;           // staging registers

    float acc[8][8];
    #pragma unroll
    for (int i = 0; i < 8; i++)
        #pragma unroll
        for (int j = 0; j < 8; j++) acc[i][j] = 0.f;

    // prologue: tile 0
    sx0 = *reinterpret_cast<const float4*>(xp0);
    sx1 = *reinterpret_cast<const float4*>(xp1);
    sw0 = *reinterpret_cast<const float4*>(W + ((size_t)wh * Cc + wr0) * Dc + wd);
    sw1 = *reinterpret_cast<const float4*>(W + ((size_t)wh * Cc + wr0 + 8) * Dc + wd);
    {
        Xs[0][xc0 + 0][xr0] = sx0.x; Xs[0][xc0 + 1][xr0] = sx0.y;
        Xs[0][xc0 + 2][xr0] = sx0.z; Xs[0][xc0 + 3][xr0] = sx0.w;
        Xs[0][xc0 + 0][xr0 + 64] = sx1.x; Xs[0][xc0 + 1][xr0 + 64] = sx1.y;
        Xs[0][xc0 + 2][xr0 + 64] = sx1.z; Xs[0][xc0 + 3][xr0 + 64] = sx1.w;
        *reinterpret_cast<float4*>(&Ws[0][wr0][wn0])     = sw0;
        *reinterpret_cast<float4*>(&Ws[0][wr0 + 8][wn0]) = sw1;
    }
    __syncthreads();

    for (int it = 0; it < NK; ++it) {
        const int buf = it & 1;
        if (it + 1 < NK) {
            const int kk = (it + 1) * TK;
            sx0 = *reinterpret_cast<const float4*>(xp0 + kk);
            sx1 = *reinterpret_cast<const float4*>(xp1 + kk);
            sw0 = *reinterpret_cast<const float4*>(W + ((size_t)wh * Cc + kk + wr0) * Dc + wd);
            sw1 = *reinterpret_cast<const float4*>(W + ((size_t)wh * Cc + kk + wr0 + 8) * Dc + wd);
        }

        #pragma unroll
        for (int c = 0; c < TK; c++) {
            float4 a0 = *reinterpret_cast<const float4*>(&Xs[buf][c][ty * 4]);
            float4 a1 = *reinterpret_cast<const float4*>(&Xs[buf][c][64 + ty * 4]);
            float4 b0 = *reinterpret_cast<const float4*>(&Ws[buf][c][tx * 4]);
            float4 b1 = *reinterpret_cast<const float4*>(&Ws[buf][c][64 + tx * 4]);
            float a[8] = {a0.x, a0.y, a0.z, a0.w, a1.x, a1.y, a1.z, a1.w};
            float bb[8] = {b0.x, b0.y, b0.z, b0.w, b1.x, b1.y, b1.z, b1.w};
            #pragma unroll
            for (int i = 0; i < 8; i++)
                #pragma unroll
                for (int j = 0; j < 8; j++)
                    acc[i][j] += a[i] * bb[j];
        }

        if (it + 1 < NK) {
            const int nb = buf ^ 1;
            Xs[nb][xc0 + 0][xr0] = sx0.x; Xs[nb][xc0 + 1][xr0] = sx0.y;
            Xs[nb][xc0 + 2][xr0] = sx0.z; Xs[nb][xc0 + 3][xr0] = sx0.w;
            Xs[nb][xc0 + 0][xr0 + 64] = sx1.x; Xs[nb][xc0 + 1][xr0 + 64] = sx1.y;
            Xs[nb][xc0 + 2][xr0 + 64] = sx1.z; Xs[nb][xc0 + 3][xr0 + 64] = sx1.w;
            *reinterpret_cast<float4*>(&Ws[nb][wr0][wn0])     = sw0;
            *reinterpret_cast<float4*>(&Ws[nb][wr0 + 8][wn0]) = sw1;
        }
        __syncthreads();
    }

    // store: n strips of 4 stay within a 64-wide head (4 | 64)
    const int nlo = tx * 4, nhi = 64 + tx * 4;
    const int h_lo = (n0h + nlo) >> 6, d_lo = (n0h + nlo) & 63;
    const int h_hi = (n0h + nhi) >> 6, d_hi = (n0h + nhi) & 63;
    #pragma unroll
    for (int i = 0; i < 8; i++) {
        int m = m0 + (i < 4 ? ty * 4 + i : 64 + ty * 4 + (i - 4));
        int b = m >> 8;                      // /Tc
        int t = m & 255;                     // %Tc
        float* Olo = Obase + (((size_t)(b * Hc + h_lo) * Tc + t) * Dc + d_lo);
        float* Ohi = Obase + (((size_t)(b * Hc + h_hi) * Tc + t) * Dc + d_hi);
        float4 o0, o1;
        o0.x = acc[i][0]; o0.y = acc[i][1]; o0.z = acc[i][2]; o0.w = acc[i][3];
        o1.x = acc[i][4]; o1.y = acc[i][5]; o1.z = acc[i][6]; o1.w = acc[i][7];
        *reinterpret_cast<float4*>(Olo) = o0;
        *reinterpret_cast<float4*>(Ohi) = o1;
    }
}

// ---------------------------------------------------------------------------
// Kernel 2: causal attention. grid = (BH, T/QB), block = QB threads.
// Thread-per-query online softmax; K/V streamed through 64KB smem in
// 128-key chunks; causally-dead chunks skipped. (unchanged — passing lineage)
// ---------------------------------------------------------------------------
constexpr int CH = 128;  // keys per chunk
constexpr int QB = 128;  // queries per CTA

__global__ void __launch_bounds__(QB, 3)
attn_kernel() {
    const int bh = blockIdx.x;
    const int b = bh / Hc;
    const int h = bh % Hc;
    const int qc = blockIdx.y;
    const int t = qc * QB + threadIdx.x;
    const int tl = threadIdx.x;

    extern __shared__ float smem[];
    float* Ks = smem;
    float* Vs = smem + CH * Dc;

    float4 q4[16];
    const float4* qg = reinterpret_cast<const float4*>(g_Q + ((size_t)bh * Tc + t) * Dc);
    #pragma unroll
    for (int i = 0; i < 16; i++) q4[i] = qg[i];

    float m = -1e30f, l = 0.f;
    float4 acc[16];
    #pragma unroll
    for (int i = 0; i < 16; i++) acc[i] = make_float4(0.f, 0.f, 0.f, 0.f);

    const float scale = 0.125f;
    const int qEnd = qc * QB + QB - 1;

    for (int c0 = 0; c0 <= qEnd; c0 += CH) {
        __syncthreads();
        const float4* kg = reinterpret_cast<const float4*>(g_K + ((size_t)bh * Tc + c0) * Dc);
        const float4* vg = reinterpret_cast<const float4*>(g_V + ((size_t)bh * Tc + c0) * Dc);
        float4* Ks4 = reinterpret_cast<float4*>(Ks);
        float4* Vs4 = reinterpret_cast<float4*>(Vs);
        #pragma unroll
        for (int i = 0; i < (CH * Dc / 4) / QB; i++) {
            Ks4[i * QB + tl] = kg[i * QB + tl];
            Vs4[i * QB + tl] = vg[i * QB + tl];
        }
        __syncthreads();

        const int nKeys = min(t - c0 + 1, CH);
        int sc = 0;

        for (; sc + 2 <= nKeys; sc += 2) {
            const float4* k0 = reinterpret_cast<const float4*>(Ks + (sc + 0) * Dc);
            const float4* k1 = reinterpret_cast<const float4*>(Ks + (sc + 1) * Dc);
            float4 d0 = make_float4(0.f, 0.f, 0.f, 0.f);
            float4 d1 = make_float4(0.f, 0.f, 0.f, 0.f);
            #pragma unroll
            for (int i = 0; i < 16; i++) {
                float4 a = q4[i];
                float4 kv0 = k0[i];
                float4 kv1 = k1[i];
                d0.x += a.x * kv0.x; d0.y += a.y * kv0.y;
                d0.z += a.z * kv0.z; d0.w += a.w * kv0.w;
                d1.x += a.x * kv1.x; d1.y += a.y * kv1.y;
                d1.z += a.z * kv1.z; d1.w += a.w * kv1.w;
            }
            float x0 = ((d0.x + d0.y) + (d0.z + d0.w)) * scale;
            float x1 = ((d1.x + d1.y) + (d1.z + d1.w)) * scale;

            float mn = fmaxf(m, fmaxf(x0, x1));
            float p0 = __expf(x0 - mn);
            float p1 = __expf(x1 - mn);
            float corr = __expf(m - mn);
            l = l * corr + p0 + p1;
            const float4* v0 = reinterpret_cast<const float4*>(Vs + (sc + 0) * Dc);
            const float4* v1 = reinterpret_cast<const float4*>(Vs + (sc + 1) * Dc);
            #pragma unroll
            for (int i = 0; i < 16; i++) {
                float4 a = acc[i];
                float4 va = v0[i];
                float4 vb = v1[i];
                a.x = a.x * corr + p0 * va.x + p1 * vb.x;
                a.y = a.y * corr + p0 * va.y + p1 * vb.y;
                a.z = a.z * corr + p0 * va.z + p1 * vb.z;
                a.w = a.w * corr + p0 * va.w + p1 * vb.w;
                acc[i] = a;
            }
            m = mn;
        }

        for (; sc < nKeys; ++sc) {
            const float4* kk = reinterpret_cast<const float4*>(Ks + sc * Dc);
            float4 d4 = make_float4(0.f, 0.f, 0.f, 0.f);
            #pragma unroll
            for (int i = 0; i < 16; i++) {
                float4 kv = kk[i];
                d4.x += q4[i].x * kv.x;
                d4.y += q4[i].y * kv.y;
                d4.z += q4[i].z * kv.z;
                d4.w += q4[i].w * kv.w;
            }
            float xv = ((d4.x + d4.y) + (d4.z + d4.w)) * scale;
            float mn = fmaxf(m, xv);
            float p = __expf(xv - mn);
            float corr = __expf(m - mn);
            l = l * corr + p;
            const float4* vv = reinterpret_cast<const float4*>(Vs + sc * Dc);
            #pragma unroll
            for (int i = 0; i < 16; i++) {
                float4 v = vv[i];
                acc[i].x = acc[i].x * corr + p * v.x;
                acc[i].y = acc[i].y * corr + p * v.y;
                acc[i].z = acc[i].z * corr + p * v.z;
                acc[i].w = acc[i].w * corr + p * v.w;
            }
            m = mn;
        }
    }

    const float inv = 1.f / l;
    float* og = g_att + ((size_t)b * Tc + t) * Cc + h * Dc;
    #pragma unroll
    for (int i = 0; i < 16; i++) {
        float4 o;
        o.x = acc[i].x * inv; o.y = acc[i].y * inv;
        o.z = acc[i].z * inv; o.w = acc[i].w * inv;
        *reinterpret_cast<float4*>(og + i * 4) = o;
    }
}

// ---------------------------------------------------------------------------
// Kernel 3: output projection  out = att @ Wp^T + bp
// Same strip-of-4 tiling + register-staged double buffering.
// grid = (Cc/128 = 3, BT/128 = 128)
// ---------------------------------------------------------------------------
__global__ void __launch_bounds__(256, 2)
proj_kernel(const float* __restrict__ Wp,
            const float* __restrict__ bp,
            float* __restrict__ out) {
    const int n0 = blockIdx.x * TN;
    const int m0 = blockIdx.y * TM;

    __shared__ float As[2][TK][TM + PAD];   // [buf][k][m]
    __shared__ float Bs[2][TK][TN + PAD];   // [buf][k][n] (= Wp transposed)

    const int tx = threadIdx.x & 15;
    const int ty = threadIdx.x >> 4;
    const int tid = threadIdx.x;

    // A: rows ar0 and ar0+64, k-cols [ac0, ac0+4)
    const int ar0 = tid >> 2;
    const int ac0 = (tid & 3) * 4;
    const float* ap0 = g_att + (size_t)(m0 + ar0) * Cc + ac0;
    const float* ap1 = g_att + (size_t)(m0 + ar0 + 64) * Cc + ac0;
    // B: n rows ar0 and ar0+64, k-cols [ac0, ac0+4)  (Wp is [n][k] row-major)
    const float* bq0 = Wp + (size_t)(n0 + ar0) * Cc + ac0;
    const float* bq1 = Wp + (size_t)(n0 + ar0 + 64) * Cc + ac0;

    float4 sa0, sa1, sb0, sb1;

    float acc[8][8];
    #pragma unroll
    for (int i = 0; i < 8; i++)
        #pragma unroll
        for (int j = 0; j < 8; j++) acc[i][j] = 0.f;

    // prologue: tile 0
    sa0 = *reinterpret_cast<const float4*>(ap0);
    sa1 = *reinterpret_cast<const float4*>(ap1);
    sb0 = *reinterpret_cast<const float4*>(bq0);
    sb1 = *reinterpret_cast<const float4*>(bq1);
    {
        As[0][ac0 + 0][ar0] = sa0.x; As[0][ac0 + 1][ar0] = sa0.y;
        As[0][ac0 + 2][ar0] = sa0.z; As[0][ac0 + 3][ar0] = sa0.w;
        As[0][ac0 + 0][ar0 + 64] = sa1.x; As[0][ac0 + 1][ar0 + 64] = sa1.y;
        As[0][ac0 + 2][ar0 + 64] = sa1.z; As[0][ac0 + 3][ar0 + 64] = sa1.w;
        Bs[0][ac0 + 0][ar0] = sb0.x; Bs[0][ac0 + 1][ar0] = sb0.y;
        Bs[0][ac0 + 2][ar0] = sb0.z; Bs[0][ac0 + 3][ar0] = sb0.w;
        Bs[0][ac0 + 0][ar0 + 64] = sb1.x; Bs[0][ac0 + 1][ar0 + 64] = sb1.y;
        Bs[0][ac0 + 2][ar0 + 64] = sb1.z; Bs[0][ac0 + 3][ar0 + 64] = sb1.w;
    }
    __syncthreads();

    for (int it = 0; it < NK; ++it) {
        const int buf = it & 1;
        if (it + 1 < NK) {
            const int kk = (it + 1) * TK;
            sa0 = *reinterpret_cast<const float4*>(ap0 + kk);
            sa1 = *reinterpret_cast<const float4*>(ap1 + kk);
            sb0 = *reinterpret_cast<const float4*>(bq0 + kk);
            sb1 = *reinterpret_cast<const float4*>(bq1 + kk);
        }

        #pragma unroll
        for (int c = 0; c < TK; c++) {
            float4 a0 = *reinterpret_cast<const float4*>(&As[buf][c][ty * 4]);
            float4 a1 = *reinterpret_cast<const float4*>(&As[buf][c][64 + ty * 4]);
            float4 b0 = *reinterpret_cast<const float4*>(&Bs[buf][c][tx * 4]);
            float4 b1 = *reinterpret_cast<const float4*>(&Bs[buf][c][64 + tx * 4]);
            float a[8] = {a0.x, a0.y, a0.z, a0.w, a1.x, a1.y, a1.z, a1.w};
            float bb[8] = {b0.x, b0.y, b0.z, b0.w, b1.x, b1.y, b1.z, b1.w};
            #pragma unroll
            for (int i = 0; i < 8; i++)
                #pragma unroll
                for (int j = 0; j < 8; j++)
                    acc[i][j] += a[i] * bb[j];
        }

        if (it + 1 < NK) {
            const int nb = buf ^ 1;
            As[nb][ac0 + 0][ar0] = sa0.x; As[nb][ac0 + 1][ar0] = sa0.y;
            As[nb][ac0 + 2][ar0] = sa0.z; As[nb][ac0 + 3][ar0] = sa0.w;
            As[nb][ac0 + 0][ar0 + 64] = sa1.x; As[nb][ac0 + 1][ar0 + 64] = sa1.y;
            As[nb][ac0 + 2][ar0 + 64] = sa1.z; As[nb][ac0 + 3][ar0 + 64] = sa1.w;
            Bs[nb][ac0 + 0][ar0] = sb0.x; Bs[nb][ac0 + 1][ar0] = sb0.y;
            Bs[nb][ac0 + 2][ar0] = sb0.z; Bs[nb][ac0 + 3][ar0] = sb0.w;
            Bs[nb][ac0 + 0][ar0 + 64] = sb1.x; Bs[nb][ac0 + 1][ar0 + 64] = sb1.y;
            Bs[nb][ac0 + 2][ar0 + 64] = sb1.z; Bs[nb][ac0 + 3][ar0 + 64] = sb1.w;
        }
        __syncthreads();
    }

    float4 bp0 = *reinterpret_cast<const float4*>(bp + n0 + tx * 4);
    float4 bp1 = *reinterpret_cast<const float4*>(bp + n0 + 64 + tx * 4);
    #pragma unroll
    for (int i = 0; i < 8; i++) {
        int m = m0 + (i < 4 ? ty * 4 + i : 64 + ty * 4 + (i - 4));
        float* Olo = out + (size_t)m * Cc + n0 + tx * 4;
        float* Ohi = out + (size_t)m * Cc + n0 + 64 + tx * 4;
        float4 o0, o1;
        o0.x = acc[i][0] + bp0.x; o0.y = acc[i][1] + bp0.y;
        o0.z = acc[i][2] + bp0.z; o0.w = acc[i][3] + bp0.w;
        o1.x = acc[i][4] + bp1.x; o1.y = acc[i][5] + bp1.y;
        o1.z = acc[i][6] + bp1.z; o1.w = acc[i][7] + bp1.w;
        *reinterpret_cast<float4*>(Olo) = o0;
        *reinterpret_cast<float4*>(Ohi) = o1;
    }
}

// ---------------------------------------------------------------------------
extern "C" void kernel_launch(void* const* d_in, const int* in_sizes, int n_in,
                              void* d_out, int out_size) {
    const float* x  = (const float*)d_in[0];
    const float* Wq = (const float*)d_in[1];
    const float* Wk = (const float*)d_in[2];
    const float* Wv = (const float*)d_in[3];
    const float* Wp = (const float*)d_in[4];
    const float* bp = (const float*)d_in[5];
    float* out = (float*)d_out;

    cudaFuncSetAttribute(attn_kernel, cudaFuncAttributeMaxDynamicSharedMemorySize,
                         2 * CH * Dc * (int)sizeof(float));

    dim3 g1(NQKV / TN, BT / TM);          // (9, 128)
    qkv_kernel<<<g1, 256>>>(x, Wq, Wk, Wv);

    dim3 g2(BH, Tc / QB);
    attn_kernel<<<g2, QB, 2 * CH * Dc * sizeof(float)>>>();

    dim3 g3(Cc / TN, BT / TM);            // (3, 128)
    proj_kernel<<<g3, 256>>>(Wp, bp, out);
}